// round 16
// baseline (speedup 1.0000x reference)
#include <cuda_runtime.h>
#include <cuda_bf16.h>
#include <math.h>
#include <stdint.h>

#define BSZ  4
#define TLEN 4096
#define CDIM 1024
#define HDIM 64
#define MTOT (BSZ * TLEN)
#define NSPLIT 2

// Projected operands, bf16 hi/lo split.
// Q (pre-scaled by 0.125*log2(e)) and K: [m][h] row-major. Vt: [h][m] (transposed).
__device__ __nv_bfloat16 g_Qhi[MTOT * HDIM], g_Qlo[MTOT * HDIM];
__device__ __nv_bfloat16 g_Khi[MTOT * HDIM], g_Klo[MTOT * HDIM];
__device__ __nv_bfloat16 g_Vthi[HDIM * MTOT], g_Vtlo[HDIM * MTOT];
// Split-KV partials.
__device__ float  g_Opart[NSPLIT * MTOT * HDIM];
__device__ float2 g_stats[NSPLIT * MTOT];
// Weights pre-split to bf16 hi/lo, [which][h][c], which: 0=Q, 1=K, 2=V.
__device__ __nv_bfloat16 g_Whi[3 * HDIM * CDIM];
__device__ __nv_bfloat16 g_Wlo[3 * HDIM * CDIM];

typedef unsigned long long u64;
typedef unsigned int u32;

// ---------------- mma.sync / cp.async helpers ----------------
__device__ __forceinline__ u32 smem_u32(const void* p) {
    u32 a;
    asm("{ .reg .u64 t; cvta.to.shared.u64 t, %1; cvt.u32.u64 %0, t; }"
        : "=r"(a) : "l"(p));
    return a;
}
__device__ __forceinline__ void ldm_x4(u32 &r0, u32 &r1, u32 &r2, u32 &r3, u32 addr) {
    asm volatile("ldmatrix.sync.aligned.m8n8.x4.shared.b16 {%0,%1,%2,%3}, [%4];"
                 : "=r"(r0), "=r"(r1), "=r"(r2), "=r"(r3) : "r"(addr));
}
__device__ __forceinline__ void mma_bf16(float* d, const u32* a, const u32* b) {
    asm volatile(
        "mma.sync.aligned.m16n8k16.row.col.f32.bf16.bf16.f32 "
        "{%0,%1,%2,%3}, {%4,%5,%6,%7}, {%8,%9}, {%0,%1,%2,%3};"
        : "+f"(d[0]), "+f"(d[1]), "+f"(d[2]), "+f"(d[3])
        : "r"(a[0]), "r"(a[1]), "r"(a[2]), "r"(a[3]), "r"(b[0]), "r"(b[1]));
}
__device__ __forceinline__ void cp_async16(u32 smem_addr, const void* gptr) {
    asm volatile("cp.async.cg.shared.global [%0], [%1], 16;"
                 :: "r"(smem_addr), "l"(gptr) : "memory");
}
#define CP_COMMIT() asm volatile("cp.async.commit_group;" ::: "memory")
#define CP_WAIT(N)  asm volatile("cp.async.wait_group %0;" :: "n"(N) : "memory")

__device__ __forceinline__ u64 pack32(u32 a, u32 b) {
    u64 r; asm("mov.b64 %0, {%1, %2};" : "=l"(r) : "r"(a), "r"(b)); return r;
}
__device__ __forceinline__ u32 cvt_bf2(float a, float b) {
    __nv_bfloat162 h = __floats2bfloat162_rn(a, b);
    return *(u32*)&h;
}
__device__ __forceinline__ float2 bf2_to_f2(u32 v) {
    __nv_bfloat162 h = *(__nv_bfloat162*)&v;
    return __bfloat1622float2(h);
}
__device__ __forceinline__ void cvt_hilo(float4 v, u64 &hi, u64 &lo) {
    u32 h01 = cvt_bf2(v.x, v.y), h23 = cvt_bf2(v.z, v.w);
    float2 f01 = bf2_to_f2(h01), f23 = bf2_to_f2(h23);
    u32 l01 = cvt_bf2(v.x - f01.x, v.y - f01.y);
    u32 l23 = cvt_bf2(v.z - f23.x, v.w - f23.y);
    hi = pack32(h01, h23);
    lo = pack32(l01, l23);
}

// ---------------------------------------------------------------------------
// Weight pre-split: fp32 -> bf16 hi/lo.
// ---------------------------------------------------------------------------
__global__ __launch_bounds__(256) void wconv_kernel(
    const float* __restrict__ Wk,
    const float* __restrict__ Wq,
    const float* __restrict__ Wv)
{
    int idx = blockIdx.x * 256 + threadIdx.x;     // 3 * 65536
    int w = idx >> 16;
    int r = idx & 0xFFFF;
    const float* src = (w == 0) ? Wq : (w == 1) ? Wk : Wv;
    float v = src[r];
    __nv_bfloat16 hi = __float2bfloat16(v);
    __nv_bfloat16 lo = __float2bfloat16(v - __bfloat162float(hi));
    g_Whi[idx] = hi;
    g_Wlo[idx] = lo;
}

// ---------------------------------------------------------------------------
// FUSED tensor-core projection (unchanged from R14-proven version).
// ---------------------------------------------------------------------------
#define PITCH 72
#define PS_AHI 0
#define PS_ALO (128 * PITCH * 2)                  // 18432
#define PS_B   (2 * 128 * PITCH * 2)              // 36864; tile t = w*2+half, 9216 B each
#define PROJ_SMEM (PS_B + 6 * 64 * PITCH * 2)     // 92160

__global__ __launch_bounds__(256) void proj_tc_kernel(const float* __restrict__ x)
{
    extern __shared__ char psm[];
    const u32 sb = smem_u32(psm);

    const int m0    = blockIdx.x * 128;
    const int tid   = threadIdx.x;
    const int lane  = tid & 31;
    const int wid   = tid >> 5;
    const int wm    = (wid & 3) * 32;
    const int wn    = (wid >> 2) * 32;

    float acc[3][2][4][4];
#pragma unroll
    for (int w = 0; w < 3; w++)
#pragma unroll
        for (int mt = 0; mt < 2; mt++)
#pragma unroll
            for (int nt = 0; nt < 4; nt++)
#pragma unroll
                for (int c = 0; c < 4; c++) acc[w][mt][nt][c] = 0.0f;

    const int arow  = (lane & 15);
    const int acol8 = (lane >> 4) << 3;
    const int brow4 = ((lane >> 4) << 3) | (lane & 7);
    const int bcol4 = ((lane >> 3) & 1) << 3;

#pragma unroll 1
    for (int chunk = 0; chunk < 16; chunk++) {
        const int kc = chunk * 64;

#pragma unroll
        for (int i = 0; i < 8; i++) {
            int idx = tid + i * 256;
            int row = idx >> 4;
            int cg  = idx & 15;
            float4 v = *(const float4*)(x + (size_t)(m0 + row) * CDIM + kc + cg * 4);
            u64 hi, lo;
            cvt_hilo(v, hi, lo);
            *(u64*)(psm + PS_AHI + row * (PITCH * 2) + cg * 8) = hi;
            *(u64*)(psm + PS_ALO + row * (PITCH * 2) + cg * 8) = lo;
        }
#pragma unroll
        for (int i = 0; i < 24; i++) {
            int idx  = tid + i * 256;
            int t    = idx >> 10;
            int rem  = idx & 1023;
            int row  = rem >> 4;
            int cg   = rem & 15;
            const __nv_bfloat16* src = (t & 1) ? g_Wlo : g_Whi;
            u64 v = *(const u64*)(src + (size_t)(t >> 1) * (HDIM * CDIM)
                                  + (size_t)row * CDIM + kc + cg * 4);
            *(u64*)(psm + PS_B + t * 9216 + row * (PITCH * 2) + cg * 8) = v;
        }
        __syncthreads();

#pragma unroll
        for (int ks = 0; ks < 4; ks++) {
            const int kb = ks * 16;
            u32 ah[2][4], al[2][4];
#pragma unroll
            for (int mt = 0; mt < 2; mt++) {
                u32 ra = (wm + mt * 16 + arow) * (PITCH * 2) + (kb + acol8) * 2;
                ldm_x4(ah[mt][0], ah[mt][1], ah[mt][2], ah[mt][3], sb + PS_AHI + ra);
                ldm_x4(al[mt][0], al[mt][1], al[mt][2], al[mt][3], sb + PS_ALO + ra);
            }
#pragma unroll
            for (int w = 0; w < 3; w++) {
                u32 bh[4][2], bl[4][2];
#pragma unroll
                for (int ntp = 0; ntp < 2; ntp++) {
                    u32 rb = (wn + ntp * 16 + brow4) * (PITCH * 2) + (kb + bcol4) * 2;
                    ldm_x4(bh[2 * ntp][0], bh[2 * ntp][1], bh[2 * ntp + 1][0],
                           bh[2 * ntp + 1][1], sb + PS_B + (2 * w) * 9216 + rb);
                    ldm_x4(bl[2 * ntp][0], bl[2 * ntp][1], bl[2 * ntp + 1][0],
                           bl[2 * ntp + 1][1], sb + PS_B + (2 * w + 1) * 9216 + rb);
                }
#pragma unroll
                for (int mt = 0; mt < 2; mt++)
#pragma unroll
                    for (int nt = 0; nt < 4; nt++) {
                        mma_bf16(acc[w][mt][nt], ah[mt], bh[nt]);
                        mma_bf16(acc[w][mt][nt], ah[mt], bl[nt]);
                        mma_bf16(acc[w][mt][nt], al[mt], bh[nt]);
                    }
            }
        }
        __syncthreads();
    }

    const int gid = lane >> 2;
    const int tig = lane & 3;
    const float qsc = 0.18033688011112042f;   // H^-0.5 * log2(e)

#pragma unroll
    for (int w = 0; w < 3; w++)
#pragma unroll
        for (int mt = 0; mt < 2; mt++)
#pragma unroll
            for (int nt = 0; nt < 4; nt++) {
                int m = m0 + wm + mt * 16 + gid;
                int n = wn + nt * 8 + 2 * tig;
                float sc = (w == 0) ? qsc : 1.0f;
                float v0 = acc[w][mt][nt][0] * sc;
                float v1 = acc[w][mt][nt][1] * sc;
                float v2 = acc[w][mt][nt][2] * sc;
                float v3 = acc[w][mt][nt][3] * sc;

                if (w == 2) {
                    __nv_bfloat16 h0 = __float2bfloat16(v0);
                    __nv_bfloat16 h1 = __float2bfloat16(v1);
                    __nv_bfloat16 h2 = __float2bfloat16(v2);
                    __nv_bfloat16 h3 = __float2bfloat16(v3);
                    g_Vthi[(size_t)n * MTOT + m]           = h0;
                    g_Vthi[(size_t)(n + 1) * MTOT + m]     = h1;
                    g_Vthi[(size_t)n * MTOT + m + 8]       = h2;
                    g_Vthi[(size_t)(n + 1) * MTOT + m + 8] = h3;
                    g_Vtlo[(size_t)n * MTOT + m]           = __float2bfloat16(v0 - __bfloat162float(h0));
                    g_Vtlo[(size_t)(n + 1) * MTOT + m]     = __float2bfloat16(v1 - __bfloat162float(h1));
                    g_Vtlo[(size_t)n * MTOT + m + 8]       = __float2bfloat16(v2 - __bfloat162float(h2));
                    g_Vtlo[(size_t)(n + 1) * MTOT + m + 8] = __float2bfloat16(v3 - __bfloat162float(h3));
                } else {
                    __nv_bfloat16* Ahi = (w == 0) ? g_Qhi : g_Khi;
                    __nv_bfloat16* Alo = (w == 0) ? g_Qlo : g_Klo;
                    u32 h01 = cvt_bf2(v0, v1);
                    float2 f01 = bf2_to_f2(h01);
                    u32 l01 = cvt_bf2(v0 - f01.x, v1 - f01.y);
                    u32 h23 = cvt_bf2(v2, v3);
                    float2 f23 = bf2_to_f2(h23);
                    u32 l23 = cvt_bf2(v2 - f23.x, v3 - f23.y);
                    *(u32*)&Ahi[(size_t)m * HDIM + n]       = h01;
                    *(u32*)&Alo[(size_t)m * HDIM + n]       = l01;
                    *(u32*)&Ahi[(size_t)(m + 8) * HDIM + n] = h23;
                    *(u32*)&Alo[(size_t)(m + 8) * HDIM + n] = l23;
                }
            }
}

// ---------------------------------------------------------------------------
// FA2 attention v2: BM=128 (256 thr, 8 warps x 16 rows), BN=64,
// cp.async double-buffered K/V, split-KV (always-equal halves).
// smem: QH/QL 18432 each; 2 KV stages of 36864 (KH/KL/VH/VL @ 9216).
// ---------------------------------------------------------------------------
#define AQH 0
#define AQL 18432
#define AKV0 36864
#define AKV_STRIDE 36864
#define ATTN_SMEM 110592

__device__ __forceinline__ void kv_prefetch(u32 sb, int kb, int st, int tid)
{
    u32 base = sb + AKV0 + st * AKV_STRIDE;
#pragma unroll
    for (int i = 0; i < 8; i++) {
        int idx = tid + i * 256;
        int t   = idx >> 9;       // 0..3 : KH,KL,VH,VL
        int rem = idx & 511;
        int row = rem >> 3;
        int cg  = rem & 7;
        const __nv_bfloat16* g;
        if (t == 0)      g = g_Khi  + (size_t)(kb + row) * HDIM + cg * 8;
        else if (t == 1) g = g_Klo  + (size_t)(kb + row) * HDIM + cg * 8;
        else if (t == 2) g = g_Vthi + (size_t)row * MTOT + kb + cg * 8;
        else             g = g_Vtlo + (size_t)row * MTOT + kb + cg * 8;
        cp_async16(base + t * 9216 + row * (PITCH * 2) + cg * 16, g);
    }
}

__global__ __launch_bounds__(256, 2) void attn_tc_kernel()
{
    extern __shared__ char csm[];
    const u32 sb = smem_u32(csm);

    const int b     = blockIdx.y;
    const int qb    = 31 - (blockIdx.x >> 1);   // longest CTAs first
    const int split = blockIdx.x & 1;
    const int j0    = (qb + 1) * split;         // nblk = 2qb+2, equal halves
    const int j1    = (qb + 1) * (split + 1);

    const int tid  = threadIdx.x;
    const int wid  = tid >> 5;
    const int lane = tid & 31;
    const int gid  = lane >> 2;
    const int tig  = lane & 3;
    const int wm   = wid * 16;
    const int m0   = b * TLEN + qb * 128;
    const int qrow0 = qb * 128;

    float* Op = g_Opart + (size_t)split * MTOT * HDIM;

    // ---- Q tile via cp.async (2048 x 16B) ----
#pragma unroll
    for (int i = 0; i < 8; i++) {
        int idx  = tid + i * 256;
        int half = idx >> 10;
        int rem  = idx & 1023;
        int row  = rem >> 3;
        int cg   = rem & 7;
        const __nv_bfloat16* src = half ? g_Qlo : g_Qhi;
        cp_async16(sb + (half ? AQL : AQH) + row * (PITCH * 2) + cg * 16,
                   src + (size_t)(m0 + row) * HDIM + cg * 8);
    }
    CP_COMMIT();
    kv_prefetch(sb, b * TLEN + j0 * 64, 0, tid);
    CP_COMMIT();

    const int arow  = (lane & 15);
    const int acol8 = (lane >> 4) << 3;
    const int brow4 = ((lane >> 4) << 3) | (lane & 7);
    const int bcol4 = ((lane >> 3) & 1) << 3;

    float o[8][4];
#pragma unroll
    for (int nt = 0; nt < 8; nt++)
#pragma unroll
        for (int c = 0; c < 4; c++) o[nt][c] = 0.0f;
    float mrow0 = -1e30f, mrow1 = -1e30f, lrow0 = 0.0f, lrow1 = 0.0f;

#pragma unroll 1
    for (int jb = j0; jb < j1; jb++) {
        const int st = (jb - j0) & 1;
        if (jb + 1 < j1) {
            kv_prefetch(sb, b * TLEN + (jb + 1) * 64, st ^ 1, tid);
            CP_COMMIT();
            CP_WAIT(1);
        } else {
            CP_WAIT(0);
        }
        __syncthreads();

        const u32 kvb = sb + AKV0 + st * AKV_STRIDE;

        // ---- S = Q K^T (log2 domain), 16 x 64 per warp ----
        float s[8][4];
#pragma unroll
        for (int nt = 0; nt < 8; nt++)
#pragma unroll
            for (int c = 0; c < 4; c++) s[nt][c] = 0.0f;

#pragma unroll
        for (int kk = 0; kk < 4; kk++) {
            u32 qh[4], ql[4];
            u32 ra = (wm + arow) * (PITCH * 2) + (kk * 16 + acol8) * 2;
            ldm_x4(qh[0], qh[1], qh[2], qh[3], sb + AQH + ra);
            ldm_x4(ql[0], ql[1], ql[2], ql[3], sb + AQL + ra);
#pragma unroll
            for (int ntp = 0; ntp < 4; ntp++) {
                u32 rb = (ntp * 16 + brow4) * (PITCH * 2) + (kk * 16 + bcol4) * 2;
                u32 bh[2][2], bl[2][2];
                ldm_x4(bh[0][0], bh[0][1], bh[1][0], bh[1][1], kvb + 0    + rb);
                ldm_x4(bl[0][0], bl[0][1], bl[1][0], bl[1][1], kvb + 9216 + rb);
                mma_bf16(s[2 * ntp],     qh, bh[0]);
                mma_bf16(s[2 * ntp],     qh, bl[0]);
                mma_bf16(s[2 * ntp],     ql, bh[0]);
                mma_bf16(s[2 * ntp + 1], qh, bh[1]);
                mma_bf16(s[2 * ntp + 1], qh, bl[1]);
                mma_bf16(s[2 * ntp + 1], ql, bh[1]);
            }
        }

        // ---- Causal mask (blocks intersecting the diagonal) ----
        if (jb >= 2 * qb) {
            const int rA = qrow0 + wm + gid;
            const int rB = rA + 8;
#pragma unroll
            for (int nt = 0; nt < 8; nt++) {
                int col = jb * 64 + nt * 8 + 2 * tig;
                if (col > rA)     s[nt][0] = -1e30f;
                if (col + 1 > rA) s[nt][1] = -1e30f;
                if (col > rB)     s[nt][2] = -1e30f;
                if (col + 1 > rB) s[nt][3] = -1e30f;
            }
        }

        // ---- Online softmax (rows gid and gid+8), log2 domain ----
        float mx0 = -1e30f, mx1 = -1e30f;
#pragma unroll
        for (int nt = 0; nt < 8; nt++) {
            mx0 = fmaxf(mx0, fmaxf(s[nt][0], s[nt][1]));
            mx1 = fmaxf(mx1, fmaxf(s[nt][2], s[nt][3]));
        }
        mx0 = fmaxf(mx0, __shfl_xor_sync(0xffffffffu, mx0, 1));
        mx0 = fmaxf(mx0, __shfl_xor_sync(0xffffffffu, mx0, 2));
        mx1 = fmaxf(mx1, __shfl_xor_sync(0xffffffffu, mx1, 1));
        mx1 = fmaxf(mx1, __shfl_xor_sync(0xffffffffu, mx1, 2));
        float mn0 = fmaxf(mrow0, mx0), mn1 = fmaxf(mrow1, mx1);
        float al0 = exp2f(mrow0 - mn0), al1 = exp2f(mrow1 - mn1);

        float rs0 = 0.0f, rs1 = 0.0f;
#pragma unroll
        for (int nt = 0; nt < 8; nt++) {
            s[nt][0] = exp2f(s[nt][0] - mn0);
            s[nt][1] = exp2f(s[nt][1] - mn0);
            s[nt][2] = exp2f(s[nt][2] - mn1);
            s[nt][3] = exp2f(s[nt][3] - mn1);
            rs0 += s[nt][0] + s[nt][1];
            rs1 += s[nt][2] + s[nt][3];
        }
        rs0 += __shfl_xor_sync(0xffffffffu, rs0, 1);
        rs0 += __shfl_xor_sync(0xffffffffu, rs0, 2);
        rs1 += __shfl_xor_sync(0xffffffffu, rs1, 1);
        rs1 += __shfl_xor_sync(0xffffffffu, rs1, 2);
        lrow0 = lrow0 * al0 + rs0;
        lrow1 = lrow1 * al1 + rs1;
        mrow0 = mn0;
        mrow1 = mn1;

#pragma unroll
        for (int nt = 0; nt < 8; nt++) {
            o[nt][0] *= al0; o[nt][1] *= al0;
            o[nt][2] *= al1; o[nt][3] *= al1;
        }

        // ---- O += P V: P C-frags repacked to A-frags (hi/lo) ----
#pragma unroll
        for (int kk = 0; kk < 4; kk++) {
            const int ja = 2 * kk, jc = 2 * kk + 1;
            u32 pah[4], pal[4];
            pah[0] = cvt_bf2(s[ja][0], s[ja][1]);
            pah[1] = cvt_bf2(s[ja][2], s[ja][3]);
            pah[2] = cvt_bf2(s[jc][0], s[jc][1]);
            pah[3] = cvt_bf2(s[jc][2], s[jc][3]);
            {
                float2 f0 = bf2_to_f2(pah[0]);
                float2 f1 = bf2_to_f2(pah[1]);
                float2 f2 = bf2_to_f2(pah[2]);
                float2 f3 = bf2_to_f2(pah[3]);
                pal[0] = cvt_bf2(s[ja][0] - f0.x, s[ja][1] - f0.y);
                pal[1] = cvt_bf2(s[ja][2] - f1.x, s[ja][3] - f1.y);
                pal[2] = cvt_bf2(s[jc][0] - f2.x, s[jc][1] - f2.y);
                pal[3] = cvt_bf2(s[jc][2] - f3.x, s[jc][3] - f3.y);
            }
#pragma unroll
            for (int ntp = 0; ntp < 4; ntp++) {
                u32 rb = (ntp * 16 + brow4) * (PITCH * 2) + (kk * 16 + bcol4) * 2;
                u32 vh[2][2], vl[2][2];
                ldm_x4(vh[0][0], vh[0][1], vh[1][0], vh[1][1], kvb + 18432 + rb);
                ldm_x4(vl[0][0], vl[0][1], vl[1][0], vl[1][1], kvb + 27648 + rb);
                mma_bf16(o[2 * ntp],     pah, vh[0]);
                mma_bf16(o[2 * ntp],     pah, vl[0]);
                mma_bf16(o[2 * ntp],     pal, vh[0]);
                mma_bf16(o[2 * ntp + 1], pah, vh[1]);
                mma_bf16(o[2 * ntp + 1], pah, vl[1]);
                mma_bf16(o[2 * ntp + 1], pal, vh[1]);
            }
        }
        __syncthreads();   // all warps done with stage st before it is refilled
    }

    // ---- Write unnormalized partial O + stats ----
#pragma unroll
    for (int nt = 0; nt < 8; nt++) {
        int n = nt * 8 + 2 * tig;
        *(float2*)&Op[(size_t)(m0 + wm + gid) * HDIM + n]     = make_float2(o[nt][0], o[nt][1]);
        *(float2*)&Op[(size_t)(m0 + wm + gid + 8) * HDIM + n] = make_float2(o[nt][2], o[nt][3]);
    }
    if (tig == 0) {
        g_stats[split * MTOT + m0 + wm + gid]     = make_float2(mrow0, lrow0);
        g_stats[split * MTOT + m0 + wm + gid + 8] = make_float2(mrow1, lrow1);
    }
}

// ---------------------------------------------------------------------------
// Merge split partials (stats are in log2 domain -> exp2f).
// ---------------------------------------------------------------------------
__global__ __launch_bounds__(256) void merge_kernel(float* __restrict__ out)
{
    int idx = blockIdx.x * 256 + threadIdx.x;
    int m = idx >> 4;
    int h = (idx & 15) * 4;

    float2 s0 = g_stats[m];
    float2 s1 = g_stats[MTOT + m];
    float mm = fmaxf(s0.x, s1.x);
    float a0 = exp2f(s0.x - mm);
    float a1 = exp2f(s1.x - mm);
    float rinv = 1.0f / (s0.y * a0 + s1.y * a1);

    float4 o0 = *(const float4*)&g_Opart[(size_t)m * HDIM + h];
    float4 o1 = *(const float4*)&g_Opart[(size_t)(MTOT + m) * HDIM + h];

    float4 r;
    r.x = (o0.x * a0 + o1.x * a1) * rinv;
    r.y = (o0.y * a0 + o1.y * a1) * rinv;
    r.z = (o0.z * a0 + o1.z * a1) * rinv;
    r.w = (o0.w * a0 + o1.w * a1) * rinv;
    *(float4*)&out[(size_t)m * HDIM + h] = r;
}

// ---------------------------------------------------------------------------
extern "C" void kernel_launch(void* const* d_in, const int* in_sizes, int n_in,
                              void* d_out, int out_size)
{
    const float* x  = (const float*)d_in[0];
    const float* Wk = (const float*)d_in[2];
    const float* Wq = (const float*)d_in[3];
    const float* Wv = (const float*)d_in[4];
    float* out = (float*)d_out;

    wconv_kernel<<<3 * HDIM * CDIM / 256, 256>>>(Wk, Wq, Wv);

    cudaFuncSetAttribute(proj_tc_kernel,
                         cudaFuncAttributeMaxDynamicSharedMemorySize, PROJ_SMEM);
    proj_tc_kernel<<<128, 256, PROJ_SMEM>>>(x);

    cudaFuncSetAttribute(attn_tc_kernel,
                         cudaFuncAttributeMaxDynamicSharedMemorySize, ATTN_SMEM);
    dim3 ga(32 * NSPLIT, 4);
    attn_tc_kernel<<<ga, 256, ATTN_SMEM>>>();

    merge_kernel<<<(MTOT * 16) / 256, 256>>>(out);
}

// round 17
// speedup vs baseline: 1.1698x; 1.1698x over previous
#include <cuda_runtime.h>
#include <cuda_bf16.h>
#include <math.h>
#include <stdint.h>

#define BSZ  4
#define TLEN 4096
#define CDIM 1024
#define HDIM 64
#define MTOT (BSZ * TLEN)
#define NSPLIT 2

// Projected operands, bf16 hi/lo split.
// Q (pre-scaled by 0.125*log2(e)) and K: [m][h] row-major. Vt: [h][m] (transposed).
__device__ __nv_bfloat16 g_Qhi[MTOT * HDIM], g_Qlo[MTOT * HDIM];
__device__ __nv_bfloat16 g_Khi[MTOT * HDIM], g_Klo[MTOT * HDIM];
__device__ __nv_bfloat16 g_Vthi[HDIM * MTOT], g_Vtlo[HDIM * MTOT];
// Split-KV partials.
__device__ float  g_Opart[NSPLIT * MTOT * HDIM];
__device__ float2 g_stats[NSPLIT * MTOT];
// Weights pre-split to bf16 hi/lo, [which][h][c], which: 0=Q, 1=K, 2=V.
__device__ __nv_bfloat16 g_Whi[3 * HDIM * CDIM];
__device__ __nv_bfloat16 g_Wlo[3 * HDIM * CDIM];

typedef unsigned long long u64;
typedef unsigned int u32;

// ---------------- mma.sync / cp.async helpers ----------------
__device__ __forceinline__ u32 smem_u32(const void* p) {
    u32 a;
    asm("{ .reg .u64 t; cvta.to.shared.u64 t, %1; cvt.u32.u64 %0, t; }"
        : "=r"(a) : "l"(p));
    return a;
}
__device__ __forceinline__ void ldm_x4(u32 &r0, u32 &r1, u32 &r2, u32 &r3, u32 addr) {
    asm volatile("ldmatrix.sync.aligned.m8n8.x4.shared.b16 {%0,%1,%2,%3}, [%4];"
                 : "=r"(r0), "=r"(r1), "=r"(r2), "=r"(r3) : "r"(addr));
}
__device__ __forceinline__ void mma_bf16(float* d, const u32* a, const u32* b) {
    asm volatile(
        "mma.sync.aligned.m16n8k16.row.col.f32.bf16.bf16.f32 "
        "{%0,%1,%2,%3}, {%4,%5,%6,%7}, {%8,%9}, {%0,%1,%2,%3};"
        : "+f"(d[0]), "+f"(d[1]), "+f"(d[2]), "+f"(d[3])
        : "r"(a[0]), "r"(a[1]), "r"(a[2]), "r"(a[3]), "r"(b[0]), "r"(b[1]));
}
__device__ __forceinline__ void cp_async16(u32 smem_addr, const void* gptr) {
    asm volatile("cp.async.cg.shared.global [%0], [%1], 16;"
                 :: "r"(smem_addr), "l"(gptr) : "memory");
}
#define CP_COMMIT() asm volatile("cp.async.commit_group;" ::: "memory")
#define CP_WAIT(N)  asm volatile("cp.async.wait_group %0;" :: "n"(N) : "memory")

__device__ __forceinline__ u64 pack32(u32 a, u32 b) {
    u64 r; asm("mov.b64 %0, {%1, %2};" : "=l"(r) : "r"(a), "r"(b)); return r;
}
__device__ __forceinline__ u32 cvt_bf2(float a, float b) {
    __nv_bfloat162 h = __floats2bfloat162_rn(a, b);
    return *(u32*)&h;
}
__device__ __forceinline__ float2 bf2_to_f2(u32 v) {
    __nv_bfloat162 h = *(__nv_bfloat162*)&v;
    return __bfloat1622float2(h);
}
__device__ __forceinline__ void cvt_hilo(float4 v, u64 &hi, u64 &lo) {
    u32 h01 = cvt_bf2(v.x, v.y), h23 = cvt_bf2(v.z, v.w);
    float2 f01 = bf2_to_f2(h01), f23 = bf2_to_f2(h23);
    u32 l01 = cvt_bf2(v.x - f01.x, v.y - f01.y);
    u32 l23 = cvt_bf2(v.z - f23.x, v.w - f23.y);
    hi = pack32(h01, h23);
    lo = pack32(l01, l23);
}

// ---------------------------------------------------------------------------
// Weight pre-split: fp32 -> bf16 hi/lo.
// ---------------------------------------------------------------------------
__global__ __launch_bounds__(256) void wconv_kernel(
    const float* __restrict__ Wk,
    const float* __restrict__ Wq,
    const float* __restrict__ Wv)
{
    int idx = blockIdx.x * 256 + threadIdx.x;     // 3 * 65536
    int w = idx >> 16;
    int r = idx & 0xFFFF;
    const float* src = (w == 0) ? Wq : (w == 1) ? Wk : Wv;
    float v = src[r];
    __nv_bfloat16 hi = __float2bfloat16(v);
    __nv_bfloat16 lo = __float2bfloat16(v - __bfloat162float(hi));
    g_Whi[idx] = hi;
    g_Wlo[idx] = lo;
}

// ---------------------------------------------------------------------------
// FUSED tensor-core projection (unchanged, R14-proven).
// ---------------------------------------------------------------------------
#define PITCH 72
#define PS_AHI 0
#define PS_ALO (128 * PITCH * 2)                  // 18432
#define PS_B   (2 * 128 * PITCH * 2)              // 36864; tile t = w*2+half, 9216 B each
#define PROJ_SMEM (PS_B + 6 * 64 * PITCH * 2)     // 92160

__global__ __launch_bounds__(256) void proj_tc_kernel(const float* __restrict__ x)
{
    extern __shared__ char psm[];
    const u32 sb = smem_u32(psm);

    const int m0    = blockIdx.x * 128;
    const int tid   = threadIdx.x;
    const int lane  = tid & 31;
    const int wid   = tid >> 5;
    const int wm    = (wid & 3) * 32;
    const int wn    = (wid >> 2) * 32;

    float acc[3][2][4][4];
#pragma unroll
    for (int w = 0; w < 3; w++)
#pragma unroll
        for (int mt = 0; mt < 2; mt++)
#pragma unroll
            for (int nt = 0; nt < 4; nt++)
#pragma unroll
                for (int c = 0; c < 4; c++) acc[w][mt][nt][c] = 0.0f;

    const int arow  = (lane & 15);
    const int acol8 = (lane >> 4) << 3;
    const int brow4 = ((lane >> 4) << 3) | (lane & 7);
    const int bcol4 = ((lane >> 3) & 1) << 3;

#pragma unroll 1
    for (int chunk = 0; chunk < 16; chunk++) {
        const int kc = chunk * 64;

#pragma unroll
        for (int i = 0; i < 8; i++) {
            int idx = tid + i * 256;
            int row = idx >> 4;
            int cg  = idx & 15;
            float4 v = *(const float4*)(x + (size_t)(m0 + row) * CDIM + kc + cg * 4);
            u64 hi, lo;
            cvt_hilo(v, hi, lo);
            *(u64*)(psm + PS_AHI + row * (PITCH * 2) + cg * 8) = hi;
            *(u64*)(psm + PS_ALO + row * (PITCH * 2) + cg * 8) = lo;
        }
#pragma unroll
        for (int i = 0; i < 24; i++) {
            int idx  = tid + i * 256;
            int t    = idx >> 10;
            int rem  = idx & 1023;
            int row  = rem >> 4;
            int cg   = rem & 15;
            const __nv_bfloat16* src = (t & 1) ? g_Wlo : g_Whi;
            u64 v = *(const u64*)(src + (size_t)(t >> 1) * (HDIM * CDIM)
                                  + (size_t)row * CDIM + kc + cg * 4);
            *(u64*)(psm + PS_B + t * 9216 + row * (PITCH * 2) + cg * 8) = v;
        }
        __syncthreads();

#pragma unroll
        for (int ks = 0; ks < 4; ks++) {
            const int kb = ks * 16;
            u32 ah[2][4], al[2][4];
#pragma unroll
            for (int mt = 0; mt < 2; mt++) {
                u32 ra = (wm + mt * 16 + arow) * (PITCH * 2) + (kb + acol8) * 2;
                ldm_x4(ah[mt][0], ah[mt][1], ah[mt][2], ah[mt][3], sb + PS_AHI + ra);
                ldm_x4(al[mt][0], al[mt][1], al[mt][2], al[mt][3], sb + PS_ALO + ra);
            }
#pragma unroll
            for (int w = 0; w < 3; w++) {
                u32 bh[4][2], bl[4][2];
#pragma unroll
                for (int ntp = 0; ntp < 2; ntp++) {
                    u32 rb = (wn + ntp * 16 + brow4) * (PITCH * 2) + (kb + bcol4) * 2;
                    ldm_x4(bh[2 * ntp][0], bh[2 * ntp][1], bh[2 * ntp + 1][0],
                           bh[2 * ntp + 1][1], sb + PS_B + (2 * w) * 9216 + rb);
                    ldm_x4(bl[2 * ntp][0], bl[2 * ntp][1], bl[2 * ntp + 1][0],
                           bl[2 * ntp + 1][1], sb + PS_B + (2 * w + 1) * 9216 + rb);
                }
#pragma unroll
                for (int mt = 0; mt < 2; mt++)
#pragma unroll
                    for (int nt = 0; nt < 4; nt++) {
                        mma_bf16(acc[w][mt][nt], ah[mt], bh[nt]);
                        mma_bf16(acc[w][mt][nt], ah[mt], bl[nt]);
                        mma_bf16(acc[w][mt][nt], al[mt], bh[nt]);
                    }
            }
        }
        __syncthreads();
    }

    const int gid = lane >> 2;
    const int tig = lane & 3;
    const float qsc = 0.18033688011112042f;   // H^-0.5 * log2(e)

#pragma unroll
    for (int w = 0; w < 3; w++)
#pragma unroll
        for (int mt = 0; mt < 2; mt++)
#pragma unroll
            for (int nt = 0; nt < 4; nt++) {
                int m = m0 + wm + mt * 16 + gid;
                int n = wn + nt * 8 + 2 * tig;
                float sc = (w == 0) ? qsc : 1.0f;
                float v0 = acc[w][mt][nt][0] * sc;
                float v1 = acc[w][mt][nt][1] * sc;
                float v2 = acc[w][mt][nt][2] * sc;
                float v3 = acc[w][mt][nt][3] * sc;

                if (w == 2) {
                    __nv_bfloat16 h0 = __float2bfloat16(v0);
                    __nv_bfloat16 h1 = __float2bfloat16(v1);
                    __nv_bfloat16 h2 = __float2bfloat16(v2);
                    __nv_bfloat16 h3 = __float2bfloat16(v3);
                    g_Vthi[(size_t)n * MTOT + m]           = h0;
                    g_Vthi[(size_t)(n + 1) * MTOT + m]     = h1;
                    g_Vthi[(size_t)n * MTOT + m + 8]       = h2;
                    g_Vthi[(size_t)(n + 1) * MTOT + m + 8] = h3;
                    g_Vtlo[(size_t)n * MTOT + m]           = __float2bfloat16(v0 - __bfloat162float(h0));
                    g_Vtlo[(size_t)(n + 1) * MTOT + m]     = __float2bfloat16(v1 - __bfloat162float(h1));
                    g_Vtlo[(size_t)n * MTOT + m + 8]       = __float2bfloat16(v2 - __bfloat162float(h2));
                    g_Vtlo[(size_t)(n + 1) * MTOT + m + 8] = __float2bfloat16(v3 - __bfloat162float(h3));
                } else {
                    __nv_bfloat16* Ahi = (w == 0) ? g_Qhi : g_Khi;
                    __nv_bfloat16* Alo = (w == 0) ? g_Qlo : g_Klo;
                    u32 h01 = cvt_bf2(v0, v1);
                    float2 f01 = bf2_to_f2(h01);
                    u32 l01 = cvt_bf2(v0 - f01.x, v1 - f01.y);
                    u32 h23 = cvt_bf2(v2, v3);
                    float2 f23 = bf2_to_f2(h23);
                    u32 l23 = cvt_bf2(v2 - f23.x, v3 - f23.y);
                    *(u32*)&Ahi[(size_t)m * HDIM + n]       = h01;
                    *(u32*)&Alo[(size_t)m * HDIM + n]       = l01;
                    *(u32*)&Ahi[(size_t)(m + 8) * HDIM + n] = h23;
                    *(u32*)&Alo[(size_t)(m + 8) * HDIM + n] = l23;
                }
            }
}

// ---------------------------------------------------------------------------
// FA2 attention: BM=64 (128 thr, 4 warps x 16 rows — R14-proven tiling),
// now with cp.async double-buffered K/V stages + async Q fill.
// smem: QH/QL 9216 each; 2 KV stages of 36864 (KH/KL/VH/VL @ 9216). 92160 B.
// grid = (64*NSPLIT, B), qb reversed (longest first), split-KV halves.
// ---------------------------------------------------------------------------
#define AQH 0
#define AQL 9216
#define AKV0 18432
#define AKV_STRIDE 36864
#define ATTN_SMEM 92160

__device__ __forceinline__ void kv_prefetch(u32 sb, int kb, int st, int tid)
{
    u32 base = sb + AKV0 + st * AKV_STRIDE;
#pragma unroll
    for (int i = 0; i < 16; i++) {
        int idx = tid + i * 128;  // 0..2047
        int t   = idx >> 9;       // 0..3 : KH,KL,VH,VL
        int rem = idx & 511;
        int row = rem >> 3;
        int cg  = rem & 7;
        const __nv_bfloat16* g;
        if (t == 0)      g = g_Khi  + (size_t)(kb + row) * HDIM + cg * 8;
        else if (t == 1) g = g_Klo  + (size_t)(kb + row) * HDIM + cg * 8;
        else if (t == 2) g = g_Vthi + (size_t)row * MTOT + kb + cg * 8;
        else             g = g_Vtlo + (size_t)row * MTOT + kb + cg * 8;
        cp_async16(base + t * 9216 + row * (PITCH * 2) + cg * 16, g);
    }
}

__global__ __launch_bounds__(128, 2) void attn_tc_kernel()
{
    extern __shared__ char csm[];
    const u32 sb = smem_u32(csm);

    const int b     = blockIdx.y;
    const int qb    = 63 - (blockIdx.x >> 1);   // longest CTAs first
    const int split = blockIdx.x & 1;
    const int nblk  = qb + 1;
    const int j0    = (nblk * split) >> 1;
    const int j1    = (nblk * (split + 1)) >> 1;

    const int tid  = threadIdx.x;
    const int wid  = tid >> 5;
    const int lane = tid & 31;
    const int gid  = lane >> 2;
    const int tig  = lane & 3;
    const int wm   = wid * 16;
    const int m0   = b * TLEN + qb * 64;

    float* Op = g_Opart + (size_t)split * MTOT * HDIM;

    if (j0 == j1) {   // empty split: neutral partials
#pragma unroll
        for (int nt = 0; nt < 8; nt++) {
            int n = nt * 8 + 2 * tig;
            *(float2*)&Op[(size_t)(m0 + wm + gid) * HDIM + n]     = make_float2(0.f, 0.f);
            *(float2*)&Op[(size_t)(m0 + wm + gid + 8) * HDIM + n] = make_float2(0.f, 0.f);
        }
        if (tig == 0) {
            g_stats[split * MTOT + m0 + wm + gid]     = make_float2(-1e30f, 0.f);
            g_stats[split * MTOT + m0 + wm + gid + 8] = make_float2(-1e30f, 0.f);
        }
        return;
    }

    // ---- Q tile via cp.async (1024 x 16B) ----
#pragma unroll
    for (int i = 0; i < 8; i++) {
        int idx  = tid + i * 128;       // 0..1023
        int half = idx >> 9;
        int rem  = idx & 511;
        int row  = rem >> 3;
        int cg   = rem & 7;
        const __nv_bfloat16* src = half ? g_Qlo : g_Qhi;
        cp_async16(sb + (half ? AQL : AQH) + row * (PITCH * 2) + cg * 16,
                   src + (size_t)(m0 + row) * HDIM + cg * 8);
    }
    CP_COMMIT();                                   // G0 = Q
    kv_prefetch(sb, b * TLEN + j0 * 64, 0, tid);
    CP_COMMIT();                                   // G1 = KV(j0)
    CP_WAIT(1);                                    // Q done (KV may be in flight)
    __syncthreads();

    const int arow  = (lane & 15);
    const int acol8 = (lane >> 4) << 3;
    const int brow4 = ((lane >> 4) << 3) | (lane & 7);
    const int bcol4 = ((lane >> 3) & 1) << 3;

    // Q fragments held in registers (R14-proven)
    u32 qh[4][4], ql[4][4];
#pragma unroll
    for (int kk = 0; kk < 4; kk++) {
        u32 ra = (wm + arow) * (PITCH * 2) + (kk * 16 + acol8) * 2;
        ldm_x4(qh[kk][0], qh[kk][1], qh[kk][2], qh[kk][3], sb + AQH + ra);
        ldm_x4(ql[kk][0], ql[kk][1], ql[kk][2], ql[kk][3], sb + AQL + ra);
    }

    float o[8][4];
#pragma unroll
    for (int nt = 0; nt < 8; nt++)
#pragma unroll
        for (int c = 0; c < 4; c++) o[nt][c] = 0.0f;
    float mrow0 = -1e30f, mrow1 = -1e30f, lrow0 = 0.0f, lrow1 = 0.0f;

#pragma unroll 1
    for (int jb = j0; jb < j1; jb++) {
        const int st = (jb - j0) & 1;
        if (jb + 1 < j1) {
            kv_prefetch(sb, b * TLEN + (jb + 1) * 64, st ^ 1, tid);
            CP_COMMIT();
            CP_WAIT(1);          // current stage resident, next in flight
        } else {
            CP_WAIT(0);
        }
        __syncthreads();

        const u32 kvb = sb + AKV0 + st * AKV_STRIDE;

        // ---- S = Q K^T (log2 domain), 16 x 64 per warp ----
        float s[8][4];
#pragma unroll
        for (int nt = 0; nt < 8; nt++)
#pragma unroll
            for (int c = 0; c < 4; c++) s[nt][c] = 0.0f;

#pragma unroll
        for (int kk = 0; kk < 4; kk++) {
#pragma unroll
            for (int ntp = 0; ntp < 4; ntp++) {
                u32 rb = (ntp * 16 + brow4) * (PITCH * 2) + (kk * 16 + bcol4) * 2;
                u32 bh[2][2], bl[2][2];
                ldm_x4(bh[0][0], bh[0][1], bh[1][0], bh[1][1], kvb + 0    + rb);
                ldm_x4(bl[0][0], bl[0][1], bl[1][0], bl[1][1], kvb + 9216 + rb);
                mma_bf16(s[2 * ntp],     qh[kk], bh[0]);
                mma_bf16(s[2 * ntp],     qh[kk], bl[0]);
                mma_bf16(s[2 * ntp],     ql[kk], bh[0]);
                mma_bf16(s[2 * ntp + 1], qh[kk], bh[1]);
                mma_bf16(s[2 * ntp + 1], qh[kk], bl[1]);
                mma_bf16(s[2 * ntp + 1], ql[kk], bh[1]);
            }
        }

        // ---- Causal mask (diagonal block only) ----
        if (jb == qb) {
#pragma unroll
            for (int nt = 0; nt < 8; nt++) {
                int col = nt * 8 + 2 * tig;
                int rA = wm + gid, rB = wm + gid + 8;
                if (col > rA)     s[nt][0] = -1e30f;
                if (col + 1 > rA) s[nt][1] = -1e30f;
                if (col > rB)     s[nt][2] = -1e30f;
                if (col + 1 > rB) s[nt][3] = -1e30f;
            }
        }

        // ---- Online softmax (rows gid and gid+8), log2 domain ----
        float mx0 = -1e30f, mx1 = -1e30f;
#pragma unroll
        for (int nt = 0; nt < 8; nt++) {
            mx0 = fmaxf(mx0, fmaxf(s[nt][0], s[nt][1]));
            mx1 = fmaxf(mx1, fmaxf(s[nt][2], s[nt][3]));
        }
        mx0 = fmaxf(mx0, __shfl_xor_sync(0xffffffffu, mx0, 1));
        mx0 = fmaxf(mx0, __shfl_xor_sync(0xffffffffu, mx0, 2));
        mx1 = fmaxf(mx1, __shfl_xor_sync(0xffffffffu, mx1, 1));
        mx1 = fmaxf(mx1, __shfl_xor_sync(0xffffffffu, mx1, 2));
        float mn0 = fmaxf(mrow0, mx0), mn1 = fmaxf(mrow1, mx1);
        float al0 = exp2f(mrow0 - mn0), al1 = exp2f(mrow1 - mn1);

        float rs0 = 0.0f, rs1 = 0.0f;
#pragma unroll
        for (int nt = 0; nt < 8; nt++) {
            s[nt][0] = exp2f(s[nt][0] - mn0);
            s[nt][1] = exp2f(s[nt][1] - mn0);
            s[nt][2] = exp2f(s[nt][2] - mn1);
            s[nt][3] = exp2f(s[nt][3] - mn1);
            rs0 += s[nt][0] + s[nt][1];
            rs1 += s[nt][2] + s[nt][3];
        }
        rs0 += __shfl_xor_sync(0xffffffffu, rs0, 1);
        rs0 += __shfl_xor_sync(0xffffffffu, rs0, 2);
        rs1 += __shfl_xor_sync(0xffffffffu, rs1, 1);
        rs1 += __shfl_xor_sync(0xffffffffu, rs1, 2);
        lrow0 = lrow0 * al0 + rs0;
        lrow1 = lrow1 * al1 + rs1;
        mrow0 = mn0;
        mrow1 = mn1;

#pragma unroll
        for (int nt = 0; nt < 8; nt++) {
            o[nt][0] *= al0; o[nt][1] *= al0;
            o[nt][2] *= al1; o[nt][3] *= al1;
        }

        // ---- O += P V: P C-frags repacked to A-frags (hi/lo) ----
#pragma unroll
        for (int kk = 0; kk < 4; kk++) {
            const int ja = 2 * kk, jc = 2 * kk + 1;
            u32 pah[4], pal[4];
            pah[0] = cvt_bf2(s[ja][0], s[ja][1]);
            pah[1] = cvt_bf2(s[ja][2], s[ja][3]);
            pah[2] = cvt_bf2(s[jc][0], s[jc][1]);
            pah[3] = cvt_bf2(s[jc][2], s[jc][3]);
            {
                float2 f0 = bf2_to_f2(pah[0]);
                float2 f1 = bf2_to_f2(pah[1]);
                float2 f2 = bf2_to_f2(pah[2]);
                float2 f3 = bf2_to_f2(pah[3]);
                pal[0] = cvt_bf2(s[ja][0] - f0.x, s[ja][1] - f0.y);
                pal[1] = cvt_bf2(s[ja][2] - f1.x, s[ja][3] - f1.y);
                pal[2] = cvt_bf2(s[jc][0] - f2.x, s[jc][1] - f2.y);
                pal[3] = cvt_bf2(s[jc][2] - f3.x, s[jc][3] - f3.y);
            }
#pragma unroll
            for (int ntp = 0; ntp < 4; ntp++) {
                u32 rb = (ntp * 16 + brow4) * (PITCH * 2) + (kk * 16 + bcol4) * 2;
                u32 vh[2][2], vl[2][2];
                ldm_x4(vh[0][0], vh[0][1], vh[1][0], vh[1][1], kvb + 18432 + rb);
                ldm_x4(vl[0][0], vl[0][1], vl[1][0], vl[1][1], kvb + 27648 + rb);
                mma_bf16(o[2 * ntp],     pah, vh[0]);
                mma_bf16(o[2 * ntp],     pah, vl[0]);
                mma_bf16(o[2 * ntp],     pal, vh[0]);
                mma_bf16(o[2 * ntp + 1], pah, vh[1]);
                mma_bf16(o[2 * ntp + 1], pah, vl[1]);
                mma_bf16(o[2 * ntp + 1], pal, vh[1]);
            }
        }
        __syncthreads();   // stage st fully consumed before it is refilled
    }

    // ---- Write unnormalized partial O + stats ----
#pragma unroll
    for (int nt = 0; nt < 8; nt++) {
        int n = nt * 8 + 2 * tig;
        *(float2*)&Op[(size_t)(m0 + wm + gid) * HDIM + n]     = make_float2(o[nt][0], o[nt][1]);
        *(float2*)&Op[(size_t)(m0 + wm + gid + 8) * HDIM + n] = make_float2(o[nt][2], o[nt][3]);
    }
    if (tig == 0) {
        g_stats[split * MTOT + m0 + wm + gid]     = make_float2(mrow0, lrow0);
        g_stats[split * MTOT + m0 + wm + gid + 8] = make_float2(mrow1, lrow1);
    }
}

// ---------------------------------------------------------------------------
// Merge split partials (stats are in log2 domain -> exp2f).
// ---------------------------------------------------------------------------
__global__ __launch_bounds__(256) void merge_kernel(float* __restrict__ out)
{
    int idx = blockIdx.x * 256 + threadIdx.x;
    int m = idx >> 4;
    int h = (idx & 15) * 4;

    float2 s0 = g_stats[m];
    float2 s1 = g_stats[MTOT + m];
    float mm = fmaxf(s0.x, s1.x);
    float a0 = exp2f(s0.x - mm);
    float a1 = exp2f(s1.x - mm);
    float rinv = 1.0f / (s0.y * a0 + s1.y * a1);

    float4 o0 = *(const float4*)&g_Opart[(size_t)m * HDIM + h];
    float4 o1 = *(const float4*)&g_Opart[(size_t)(MTOT + m) * HDIM + h];

    float4 r;
    r.x = (o0.x * a0 + o1.x * a1) * rinv;
    r.y = (o0.y * a0 + o1.y * a1) * rinv;
    r.z = (o0.z * a0 + o1.z * a1) * rinv;
    r.w = (o0.w * a0 + o1.w * a1) * rinv;
    *(float4*)&out[(size_t)m * HDIM + h] = r;
}

// ---------------------------------------------------------------------------
extern "C" void kernel_launch(void* const* d_in, const int* in_sizes, int n_in,
                              void* d_out, int out_size)
{
    const float* x  = (const float*)d_in[0];
    const float* Wk = (const float*)d_in[2];
    const float* Wq = (const float*)d_in[3];
    const float* Wv = (const float*)d_in[4];
    float* out = (float*)d_out;

    wconv_kernel<<<3 * HDIM * CDIM / 256, 256>>>(Wk, Wq, Wv);

    cudaFuncSetAttribute(proj_tc_kernel,
                         cudaFuncAttributeMaxDynamicSharedMemorySize, PROJ_SMEM);
    proj_tc_kernel<<<128, 256, PROJ_SMEM>>>(x);

    cudaFuncSetAttribute(attn_tc_kernel,
                         cudaFuncAttributeMaxDynamicSharedMemorySize, ATTN_SMEM);
    dim3 ga(64 * NSPLIT, 4);
    attn_tc_kernel<<<ga, 128, ATTN_SMEM>>>();

    merge_kernel<<<(MTOT * 16) / 256, 256>>>(out);
}